// round 11
// baseline (speedup 1.0000x reference)
#include <cuda_runtime.h>
#include <cuda_fp16.h>
#include <math.h>
#include <stdint.h>

#define NN 50000
#define NE 800000
#define DHID 128
#define NH 4
#define DHEAD 32
#define OUTD 512
#define NEG_SLOPE 0.2f
#define EPSV 1e-9f

// chunk boundaries (divisible by 8 and 64, except final)
#define NCHUNK 4
static const int CB[NCHUNK + 1] = {0, 12544, 25088, 37632, 50000};

// GEMM smem layout (floats): 3 stages A[64][20] + 3 stages B[16][132]
#define A_STRIDE 20
#define B_STRIDE 132
#define A_STAGE (64 * A_STRIDE)
#define B_STAGE (16 * B_STRIDE)
#define SMEM_FLOATS (3 * A_STAGE + 3 * B_STAGE)
#define SMEM_BYTES (SMEM_FLOATS * 4)      // 40704

// ---------------- scratch (device globals; no allocation) ----------------
__device__ __half g_Whh0[NN * DHID];
__device__ __half g_Whh1[NN * DHID];
__device__ float g_el0[NN * NH];
__device__ float g_er0[NN * NH];
__device__ float g_el1[NN * NH];
__device__ float g_er1[NN * NH];
__device__ float g_z[NN * DHID];
__device__ float g_z2[NN * DHEAD];
__device__ int   g_cnt[NN];
__device__ int   g_rowptr[NN + 1];
__device__ int   g_epos[NE];
__device__ int   g_csrc[NE];

__device__ __forceinline__ float lrelu(float x) {
    return x > 0.0f ? x : NEG_SLOPE * x;
}

__device__ __forceinline__ uint32_t f2tf32(float x) {
    uint32_t u;
    asm("cvt.rna.tf32.f32 %0, %1;" : "=r"(u) : "f"(x));
    return u;
}

__device__ __forceinline__ void mma_tf32(float* c, const uint32_t* a, const uint32_t* b) {
    asm volatile(
        "mma.sync.aligned.m16n8k8.row.col.f32.tf32.tf32.f32 "
        "{%0,%1,%2,%3}, {%4,%5,%6,%7}, {%8,%9}, {%0,%1,%2,%3};"
        : "+f"(c[0]), "+f"(c[1]), "+f"(c[2]), "+f"(c[3])
        : "r"(a[0]), "r"(a[1]), "r"(a[2]), "r"(a[3]), "r"(b[0]), "r"(b[1]));
}

__device__ __forceinline__ uint32_t su(const void* p) {
    return (uint32_t)__cvta_generic_to_shared(p);
}

__device__ __forceinline__ void cp16(uint32_t dst, const void* src, bool p) {
    int sz = p ? 16 : 0;
    asm volatile("cp.async.cg.shared.global [%0], [%1], 16, %2;"
                 :: "r"(dst), "l"(src), "r"(sz));
}

// ================= tensor-core GEMM (tf32 mma.sync) =================
// Block tile 64x128, 8 warps (2m x 4n), 3-stage cp.async.
// FUSE=1: writes fp16 WhOut + elOut/erOut (grid.x must be 1, N==128); no fp32 C.
// FUSE=0: writes fp32 C (+bias).  rowOff: global row offset of this launch.
template <int FUSE>
__global__ void __launch_bounds__(256, 3)
gemm_tc(const float* __restrict__ A, const float* __restrict__ B,
        const float* __restrict__ bias, float* __restrict__ C,
        int M, int N, int K,
        const float* __restrict__ al, const float* __restrict__ ar,
        int rowOff, __half* __restrict__ WhOut,
        float* __restrict__ elOut, float* __restrict__ erOut) {
    extern __shared__ float smem[];

    const int tid = threadIdx.x;
    const int wid = tid >> 5, lane = tid & 31;
    const int g = lane >> 2, t = lane & 3;
    const int wm = wid & 1;
    const int wn = wid >> 1;
    const int rowBase = rowOff + blockIdx.y * 64;
    const int colBase = blockIdx.x * 128;

    const int aRow = tid >> 2, aK0 = (tid & 3) * 4;
    const int bK0 = tid >> 5, bN0 = (tid & 31) * 4;
    const bool ap = (rowBase + aRow) < M;
    const float* aSrc = A + (size_t)(ap ? rowBase + aRow : 0) * K + aK0;
    const float* bSrc0 = B + (size_t)bK0 * N + colBase + bN0;
    const float* bSrc1 = B + (size_t)(bK0 + 8) * N + colBase + bN0;

    float acc[2][4][4];
#pragma unroll
    for (int mf = 0; mf < 2; mf++)
#pragma unroll
        for (int nf = 0; nf < 4; nf++)
#pragma unroll
            for (int r = 0; r < 4; r++) acc[mf][nf][r] = 0.0f;

    const int nStages = K >> 4;

    uint32_t aDst = su(smem + aRow * A_STRIDE + aK0);
    uint32_t bDst0 = su(smem + 3 * A_STAGE + bK0 * B_STRIDE + bN0);
    uint32_t bDst1 = su(smem + 3 * A_STAGE + (bK0 + 8) * B_STRIDE + bN0);

#pragma unroll
    for (int s = 0; s < 2; s++) {
        int k0g = s * 16;
        cp16(aDst + s * A_STAGE * 4, aSrc + k0g, ap);
        cp16(bDst0 + s * B_STAGE * 4, bSrc0 + (size_t)k0g * N, true);
        cp16(bDst1 + s * B_STAGE * 4, bSrc1 + (size_t)k0g * N, true);
        asm volatile("cp.async.commit_group;");
    }

    for (int st = 0; st < nStages; st++) {
        if (nStages - st >= 2) asm volatile("cp.async.wait_group 1;" ::: "memory");
        else                   asm volatile("cp.async.wait_group 0;" ::: "memory");
        __syncthreads();

        const int cur = st % 3;
        const float* Asf = smem + cur * A_STAGE;
        const float* Bsf = smem + 3 * A_STAGE + cur * B_STAGE;

#pragma unroll
        for (int kk = 0; kk < 2; kk++) {
            const int k0 = kk * 8;
            uint32_t af[2][4], bf[4][2];
#pragma unroll
            for (int mf = 0; mf < 2; mf++) {
                int r0 = wm * 32 + mf * 16 + g;
                af[mf][0] = f2tf32(Asf[r0 * A_STRIDE + k0 + t]);
                af[mf][1] = f2tf32(Asf[(r0 + 8) * A_STRIDE + k0 + t]);
                af[mf][2] = f2tf32(Asf[r0 * A_STRIDE + k0 + t + 4]);
                af[mf][3] = f2tf32(Asf[(r0 + 8) * A_STRIDE + k0 + t + 4]);
            }
#pragma unroll
            for (int nf = 0; nf < 4; nf++) {
                int n0 = wn * 32 + nf * 8 + g;
                bf[nf][0] = f2tf32(Bsf[(k0 + t) * B_STRIDE + n0]);
                bf[nf][1] = f2tf32(Bsf[(k0 + t + 4) * B_STRIDE + n0]);
            }
#pragma unroll
            for (int mf = 0; mf < 2; mf++)
#pragma unroll
                for (int nf = 0; nf < 4; nf++)
                    mma_tf32(acc[mf][nf], af[mf], bf[nf]);
        }

        if (st + 2 < nStages) {
            int s = (st + 2) % 3;
            int k0g = (st + 2) * 16;
            cp16(aDst + s * A_STAGE * 4, aSrc + k0g, ap);
            cp16(bDst0 + s * B_STAGE * 4, bSrc0 + (size_t)k0g * N, true);
            cp16(bDst1 + s * B_STAGE * 4, bSrc1 + (size_t)k0g * N, true);
            asm volatile("cp.async.commit_group;");
        }
    }

    if (!FUSE) {
#pragma unroll
        for (int mf = 0; mf < 2; mf++) {
            int row0 = rowBase + wm * 32 + mf * 16 + g;
#pragma unroll
            for (int nf = 0; nf < 4; nf++) {
                int col = colBase + wn * 32 + nf * 8 + 2 * t;
                float b0 = bias ? bias[col] : 0.f;
                float b1 = bias ? bias[col + 1] : 0.f;
                if (row0 < M) {
                    float2 v = make_float2(acc[mf][nf][0] + b0, acc[mf][nf][1] + b1);
                    *(float2*)(C + (size_t)row0 * N + col) = v;
                }
                if (row0 + 8 < M) {
                    float2 v = make_float2(acc[mf][nf][2] + b0, acc[mf][nf][3] + b1);
                    *(float2*)(C + (size_t)(row0 + 8) * N + col) = v;
                }
            }
        }
    } else {
        float elp[2][2] = {}, erp[2][2] = {};
#pragma unroll
        for (int nf = 0; nf < 4; nf++) {
            int col = wn * 32 + nf * 8 + 2 * t;
            float la0 = al[col], la1 = al[col + 1];
            float ra0 = ar[col], ra1 = ar[col + 1];
#pragma unroll
            for (int mf = 0; mf < 2; mf++) {
                elp[mf][0] += acc[mf][nf][0] * la0 + acc[mf][nf][1] * la1;
                elp[mf][1] += acc[mf][nf][2] * la0 + acc[mf][nf][3] * la1;
                erp[mf][0] += acc[mf][nf][0] * ra0 + acc[mf][nf][1] * ra1;
                erp[mf][1] += acc[mf][nf][2] * ra0 + acc[mf][nf][3] * ra1;
                int row0 = rowBase + wm * 32 + mf * 16 + g;
                if (row0 < M) {
                    __half2 hv = __floats2half2_rn(acc[mf][nf][0], acc[mf][nf][1]);
                    *(__half2*)(WhOut + (size_t)row0 * DHID + col) = hv;
                }
                if (row0 + 8 < M) {
                    __half2 hv = __floats2half2_rn(acc[mf][nf][2], acc[mf][nf][3]);
                    *(__half2*)(WhOut + (size_t)(row0 + 8) * DHID + col) = hv;
                }
            }
        }
#pragma unroll
        for (int mf = 0; mf < 2; mf++)
#pragma unroll
            for (int rh = 0; rh < 2; rh++) {
                float v = elp[mf][rh];
                v += __shfl_xor_sync(0xFFFFFFFFu, v, 1);
                v += __shfl_xor_sync(0xFFFFFFFFu, v, 2);
                elp[mf][rh] = v;
                float w = erp[mf][rh];
                w += __shfl_xor_sync(0xFFFFFFFFu, w, 1);
                w += __shfl_xor_sync(0xFFFFFFFFu, w, 2);
                erp[mf][rh] = w;
            }
        if (t == 0) {
#pragma unroll
            for (int mf = 0; mf < 2; mf++)
#pragma unroll
                for (int rh = 0; rh < 2; rh++) {
                    int gr = rowBase + wm * 32 + mf * 16 + g + rh * 8;
                    if (gr < M) {
                        elOut[gr * NH + wn] = elp[mf][rh];
                        erOut[gr * NH + wn] = erp[mf][rh];
                    }
                }
        }
    }
}

// ================= CSR build (int4-vectorized, epos-based) =================
__global__ void k_count(const int4* __restrict__ dst4) {
    int i = blockIdx.x * blockDim.x + threadIdx.x;
    if (i >= NE / 4) return;
    int4 d = dst4[i];
    int4 p;
    p.x = atomicAdd(&g_cnt[d.x], 1);
    p.y = atomicAdd(&g_cnt[d.y], 1);
    p.z = atomicAdd(&g_cnt[d.z], 1);
    p.w = atomicAdd(&g_cnt[d.w], 1);
    ((int4*)g_epos)[i] = p;
}

__global__ void k_scan() {
    __shared__ int warpsum[32];
    const int T = 1024;
    const int CH = (NN + T - 1) / T;
    int t = threadIdx.x;
    int lane = t & 31, wid = t >> 5;
    int lo = t * CH;
    int hi = lo + CH; if (hi > NN) hi = NN;
    if (lo > NN) lo = NN;
    int s = 0;
    for (int i = lo; i < hi; i++) s += g_cnt[i];
    int v = s;
#pragma unroll
    for (int o = 1; o < 32; o <<= 1) {
        int u = __shfl_up_sync(0xFFFFFFFFu, v, o);
        if (lane >= o) v += u;
    }
    if (lane == 31) warpsum[wid] = v;
    __syncthreads();
    if (wid == 0) {
        int w = warpsum[lane];
#pragma unroll
        for (int o = 1; o < 32; o <<= 1) {
            int u = __shfl_up_sync(0xFFFFFFFFu, w, o);
            if (lane >= o) w += u;
        }
        warpsum[lane] = w;
    }
    __syncthreads();
    int excl = v - s + (wid > 0 ? warpsum[wid - 1] : 0);
    int run = excl;
    for (int i = lo; i < hi; i++) {
        g_rowptr[i] = run;
        run += g_cnt[i];
    }
    if (t == T - 1) g_rowptr[NN] = run;
}

__global__ void k_fill(const int4* __restrict__ src4, const int4* __restrict__ dst4) {
    int i = blockIdx.x * blockDim.x + threadIdx.x;
    if (i >= NE / 4) return;
    int4 s = src4[i];
    int4 d = dst4[i];
    int4 p = ((const int4*)g_epos)[i];
    g_csrc[g_rowptr[d.x] + p.x] = s.x;
    g_csrc[g_rowptr[d.y] + p.y] = s.y;
    g_csrc[g_rowptr[d.z] + p.z] = s.z;
    g_csrc[g_rowptr[d.w] + p.w] = s.w;
}

// ========== fused softmax + aggregate (R7 form: warp/node, smem exp stage) ====
template <int LAYER>
__global__ void k_gat_agg(const float* __restrict__ bias,
                          const __half* __restrict__ Wh,
                          const float* __restrict__ el,
                          const float* __restrict__ er,
                          int nodeOff, int nodeEnd) {
    __shared__ float exsAll[8][128];
    int wIn = threadIdx.x >> 5;
    int n = nodeOff + (blockIdx.x << 3) + wIn;
    if (n >= nodeEnd) return;
    float* exsw = exsAll[wIn];
    int lane = threadIdx.x & 31;
    int myh = lane >> 3;
    int beg = g_rowptr[n], end = g_rowptr[n + 1];
    float4 er4 = *(const float4*)(er + n * NH);

    float ax = 0.f, ay = 0.f, az = 0.f, aw = 0.f;
    float se0 = 0.f, se1 = 0.f, se2 = 0.f, se3 = 0.f;
    const __half* WhBase = Wh + (size_t)(lane * 4);

    for (int base = beg; base < end; base += 32) {
        int cnt = end - base; if (cnt > 32) cnt = 32;
        int sv = 0;
        float4 elv = make_float4(0.f, 0.f, 0.f, 0.f);
        if (lane < cnt) {
            sv = g_csrc[base + lane];
            elv = *(const float4*)(el + sv * NH);
        }
        float e0 = __expf(lrelu(elv.x + er4.x));
        float e1 = __expf(lrelu(elv.y + er4.y));
        float e2 = __expf(lrelu(elv.z + er4.z));
        float e3 = __expf(lrelu(elv.w + er4.w));
        if (lane >= cnt) { e0 = e1 = e2 = e3 = 0.f; }
        se0 += e0; se1 += e1; se2 += e2; se3 += e3;
        __syncwarp();
        *(float4*)&exsw[lane * 4] = make_float4(e0, e1, e2, e3);
        __syncwarp();
#pragma unroll 8
        for (int j = 0; j < cnt; j++) {
            int s = __shfl_sync(0xFFFFFFFFu, sv, j);
            float exh = exsw[j * 4 + myh];
            uint2 u = *(const uint2*)(WhBase + (size_t)s * DHID);
            float2 f0 = __half22float2(*(__half2*)&u.x);
            float2 f1 = __half22float2(*(__half2*)&u.y);
            ax = fmaf(exh, f0.x, ax);
            ay = fmaf(exh, f0.y, ay);
            az = fmaf(exh, f1.x, az);
            aw = fmaf(exh, f1.y, aw);
        }
    }
#pragma unroll
    for (int o = 16; o > 0; o >>= 1) {
        se0 += __shfl_xor_sync(0xFFFFFFFFu, se0, o);
        se1 += __shfl_xor_sync(0xFFFFFFFFu, se1, o);
        se2 += __shfl_xor_sync(0xFFFFFFFFu, se2, o);
        se3 += __shfl_xor_sync(0xFFFFFFFFu, se3, o);
    }
    float seh = myh < 2 ? (myh == 0 ? se0 : se1) : (myh == 2 ? se2 : se3);
    float r = 1.0f / (seh + EPSV);
    ax *= r; ay *= r; az *= r; aw *= r;

    if (LAYER == 1) {
        int d = lane * 4;
        float4 v;
        v.x = ax + bias[d + 0];
        v.y = ay + bias[d + 1];
        v.z = az + bias[d + 2];
        v.w = aw + bias[d + 3];
        v.x = v.x > 0.f ? v.x : (__expf(v.x) - 1.0f);
        v.y = v.y > 0.f ? v.y : (__expf(v.y) - 1.0f);
        v.z = v.z > 0.f ? v.z : (__expf(v.z) - 1.0f);
        v.w = v.w > 0.f ? v.w : (__expf(v.w) - 1.0f);
        *(float4*)(g_z + (size_t)n * DHID + d) = v;
    } else {
        int d = lane * 4;
        ax += bias[d + 0]; ay += bias[d + 1]; az += bias[d + 2]; aw += bias[d + 3];
#pragma unroll
        for (int o = 8; o <= 16; o <<= 1) {
            ax += __shfl_xor_sync(0xFFFFFFFFu, ax, o);
            ay += __shfl_xor_sync(0xFFFFFFFFu, ay, o);
            az += __shfl_xor_sync(0xFFFFFFFFu, az, o);
            aw += __shfl_xor_sync(0xFFFFFFFFu, aw, o);
        }
        if (lane < 8) {
            float4 v = make_float4(0.25f * ax, 0.25f * ay, 0.25f * az, 0.25f * aw);
            *(float4*)(g_z2 + (size_t)n * DHEAD + lane * 4) = v;
        }
    }
}

// ---------------- streams/events + func attrs ----------------
static cudaStream_t g_s2;
static cudaEvent_t g_evFork, g_evCsr, g_evBend;
static cudaEvent_t g_evA1[NCHUNK], g_evG2[NCHUNK], g_evA2[NCHUNK];
struct HostInit {
    HostInit() {
        cudaStreamCreateWithFlags(&g_s2, cudaStreamNonBlocking);
        cudaEventCreateWithFlags(&g_evFork, cudaEventDisableTiming);
        cudaEventCreateWithFlags(&g_evCsr, cudaEventDisableTiming);
        cudaEventCreateWithFlags(&g_evBend, cudaEventDisableTiming);
        for (int k = 0; k < NCHUNK; k++) {
            cudaEventCreateWithFlags(&g_evA1[k], cudaEventDisableTiming);
            cudaEventCreateWithFlags(&g_evG2[k], cudaEventDisableTiming);
            cudaEventCreateWithFlags(&g_evA2[k], cudaEventDisableTiming);
        }
        cudaFuncSetAttribute(gemm_tc<0>, cudaFuncAttributeMaxDynamicSharedMemorySize, SMEM_BYTES);
        cudaFuncSetAttribute(gemm_tc<1>, cudaFuncAttributeMaxDynamicSharedMemorySize, SMEM_BYTES);
    }
};
static HostInit g_hostInit;

// ================= launch =================
extern "C" void kernel_launch(void* const* d_in, const int* in_sizes, int n_in,
                              void* d_out, int out_size) {
    const float* h   = (const float*)d_in[0];
    const int*   src = (const int*)d_in[1];
    const int*   dst = (const int*)d_in[2];
    const float* W1  = (const float*)d_in[3];
    const float* al1 = (const float*)d_in[4];
    const float* ar1 = (const float*)d_in[5];
    const float* b1  = (const float*)d_in[6];
    const float* W2  = (const float*)d_in[7];
    const float* al2 = (const float*)d_in[8];
    const float* ar2 = (const float*)d_in[9];
    const float* b2  = (const float*)d_in[10];
    const float* Wp  = (const float*)d_in[11];
    const float* bp  = (const float*)d_in[12];
    float* out = (float*)d_out;

    float *p_z, *p_z2, *p_el0, *p_er0, *p_el1, *p_er1;
    __half *p_Wh0, *p_Wh1;
    int *p_cnt;
    cudaGetSymbolAddress((void**)&p_z,   g_z);
    cudaGetSymbolAddress((void**)&p_z2,  g_z2);
    cudaGetSymbolAddress((void**)&p_cnt, g_cnt);
    cudaGetSymbolAddress((void**)&p_Wh0, g_Whh0);
    cudaGetSymbolAddress((void**)&p_Wh1, g_Whh1);
    cudaGetSymbolAddress((void**)&p_el0, g_el0);
    cudaGetSymbolAddress((void**)&p_er0, g_er0);
    cudaGetSymbolAddress((void**)&p_el1, g_el1);
    cudaGetSymbolAddress((void**)&p_er1, g_er1);

    const int TPB = 256;
    int gEdge4 = (NE / 4 + TPB - 1) / TPB;

    // per-chunk grids
    int aggBlocks[NCHUNK], gemmBlocks[NCHUNK];
    for (int k = 0; k < NCHUNK; k++) {
        int len = CB[k + 1] - CB[k];
        aggBlocks[k]  = (len + 7) / 8;
        gemmBlocks[k] = (len + 63) / 64;
    }

    // ---- fork: CSR build on side stream, GEMM1 on main stream ----
    cudaEventRecord(g_evFork, 0);
    cudaStreamWaitEvent(g_s2, g_evFork, 0);
    cudaMemsetAsync(p_cnt, 0, NN * sizeof(int), g_s2);
    k_count<<<gEdge4, TPB, 0, g_s2>>>((const int4*)dst);
    k_scan<<<1, 1024, 0, g_s2>>>();
    k_fill<<<gEdge4, TPB, 0, g_s2>>>((const int4*)src, (const int4*)dst);
    cudaEventRecord(g_evCsr, g_s2);

    // ===== GEMM1 (full) on main =====
    gemm_tc<1><<<dim3(1, (NN + 63) / 64), 256, SMEM_BYTES>>>(
        h, W1, nullptr, nullptr, NN, DHID, DHID, al1, ar1, 0, p_Wh0, p_el0, p_er0);

    // ===== agg1 chunks on main; GEMM2 chunks trail on side =====
    cudaStreamWaitEvent(0, g_evCsr, 0);
    for (int k = 0; k < NCHUNK; k++) {
        k_gat_agg<1><<<aggBlocks[k], 256>>>(b1, p_Wh0, p_el0, p_er0, CB[k], CB[k + 1]);
        cudaEventRecord(g_evA1[k], 0);
        cudaStreamWaitEvent(g_s2, g_evA1[k], 0);
        gemm_tc<1><<<dim3(1, gemmBlocks[k]), 256, SMEM_BYTES, g_s2>>>(
            p_z, W2, nullptr, nullptr, NN, DHID, DHID, al2, ar2, CB[k], p_Wh1, p_el1, p_er1);
        cudaEventRecord(g_evG2[k], g_s2);
    }

    // ===== agg2 chunks on main (need ALL of GEMM2); proj chunks trail on side ====
    cudaStreamWaitEvent(0, g_evG2[NCHUNK - 1], 0);
    for (int k = 0; k < NCHUNK; k++) {
        k_gat_agg<2><<<aggBlocks[k], 256>>>(b2, p_Wh1, p_el1, p_er1, CB[k], CB[k + 1]);
        cudaEventRecord(g_evA2[k], 0);
        cudaStreamWaitEvent(g_s2, g_evA2[k], 0);
        gemm_tc<0><<<dim3(OUTD / 128, gemmBlocks[k]), 256, SMEM_BYTES, g_s2>>>(
            p_z2, Wp, bp, out, NN, OUTD, DHEAD, nullptr, nullptr, CB[k],
            nullptr, nullptr, nullptr);
    }
    cudaEventRecord(g_evBend, g_s2);
    cudaStreamWaitEvent(0, g_evBend, 0);
}

// round 12
// speedup vs baseline: 1.2652x; 1.2652x over previous
#include <cuda_runtime.h>
#include <cuda_fp16.h>
#include <math.h>
#include <stdint.h>

#define NN 50000
#define NE 800000
#define DHID 128
#define NH 4
#define DHEAD 32
#define OUTD 512
#define NEG_SLOPE 0.2f
#define EPSV 1e-9f

// GEMM smem layout (floats): 3 stages A[64][20] + 3 stages B[16][132]
#define A_STRIDE 20
#define B_STRIDE 132
#define A_STAGE (64 * A_STRIDE)           // 1280
#define B_STAGE (16 * B_STRIDE)           // 2112
#define SMEM_FLOATS (3 * A_STAGE + 3 * B_STAGE)
#define SMEM_BYTES (SMEM_FLOATS * 4)      // 40704

// ---------------- scratch (device globals; no allocation) ----------------
__device__ __half g_Whh[NN * DHID];   // fp16 message payload
__device__ float g_z[NN * DHID];      // tf32-rounded ELU output
__device__ float g_el[NN * NH];
__device__ float g_er[NN * NH];
__device__ float g_z2[NN * DHEAD];    // tf32-rounded layer-2 mean output
__device__ int   g_cnt[NN];
__device__ int   g_rowptr[NN + 1];
__device__ int   g_epos[NE];
__device__ int   g_csrc[NE];
__device__ float g_W1t[DHID * DHID];  // tf32-rounded weights
__device__ float g_W2t[DHID * DHID];
__device__ float g_Wpt[DHEAD * OUTD];

__device__ __forceinline__ float lrelu(float x) {
    return x > 0.0f ? x : NEG_SLOPE * x;
}

__device__ __forceinline__ uint32_t f2tf32(float x) {
    uint32_t u;
    asm("cvt.rna.tf32.f32 %0, %1;" : "=r"(u) : "f"(x));
    return u;
}

__device__ __forceinline__ float round_tf32(float x) {
    return __uint_as_float(f2tf32(x));
}

__device__ __forceinline__ void mma_tf32(float* c, const uint32_t* a, const uint32_t* b) {
    asm volatile(
        "mma.sync.aligned.m16n8k8.row.col.f32.tf32.tf32.f32 "
        "{%0,%1,%2,%3}, {%4,%5,%6,%7}, {%8,%9}, {%0,%1,%2,%3};"
        : "+f"(c[0]), "+f"(c[1]), "+f"(c[2]), "+f"(c[3])
        : "r"(a[0]), "r"(a[1]), "r"(a[2]), "r"(a[3]), "r"(b[0]), "r"(b[1]));
}

__device__ __forceinline__ uint32_t su(const void* p) {
    return (uint32_t)__cvta_generic_to_shared(p);
}

__device__ __forceinline__ void cp16(uint32_t dst, const void* src, bool p) {
    int sz = p ? 16 : 0;
    asm volatile("cp.async.cg.shared.global [%0], [%1], 16, %2;"
                 :: "r"(dst), "l"(src), "r"(sz));
}

// ============ weight pre-rounding (one tiny kernel, runs once per launch) ====
__global__ void k_round_weights(const float* __restrict__ W1,
                                const float* __restrict__ W2,
                                const float* __restrict__ Wp) {
    int i = blockIdx.x * blockDim.x + threadIdx.x;   // 0..49151
    if (i < 16384) {
        g_W1t[i] = round_tf32(W1[i]);
    } else if (i < 32768) {
        g_W2t[i - 16384] = round_tf32(W2[i - 16384]);
    } else if (i < 49152) {
        g_Wpt[i - 32768] = round_tf32(Wp[i - 32768]);
    }
}

// ================= tensor-core GEMM (tf32 mma.sync) =================
// Block tile 64x128, 8 warps (2m x 4n) of 32x32 warp tiles, 3-stage cp.async.
// CVTA: convert A fragments to tf32 at load (else A is pre-rounded).
// B is always pre-rounded (no cvt).
// FUSE=1: writes fp16 g_Whh + g_el/g_er (grid.x must be 1, N==128); no fp32 C.
// FUSE=0: writes fp32 C (+bias).  Requires K % 16 == 0, K >= 32, N % 128 == 0.
template <int FUSE, int CVTA>
__global__ void __launch_bounds__(256, 3)
gemm_tc(const float* __restrict__ A, const float* __restrict__ B,
        const float* __restrict__ bias, float* __restrict__ C,
        int M, int N, int K,
        const float* __restrict__ al, const float* __restrict__ ar) {
    extern __shared__ float smem[];

    const int tid = threadIdx.x;
    const int wid = tid >> 5, lane = tid & 31;
    const int g = lane >> 2, t = lane & 3;
    const int wm = wid & 1;               // 2 warp rows x 32
    const int wn = wid >> 1;              // 4 warp cols x 32
    const int rowBase = blockIdx.y * 64;
    const int colBase = blockIdx.x * 128;

    const int aRow = tid >> 2, aK0 = (tid & 3) * 4;
    const int bK0 = tid >> 5, bN0 = (tid & 31) * 4;
    const bool ap = (rowBase + aRow) < M;
    const float* aSrc = A + (size_t)(ap ? rowBase + aRow : 0) * K + aK0;
    const float* bSrc0 = B + (size_t)bK0 * N + colBase + bN0;
    const float* bSrc1 = B + (size_t)(bK0 + 8) * N + colBase + bN0;

    float acc[2][4][4];
#pragma unroll
    for (int mf = 0; mf < 2; mf++)
#pragma unroll
        for (int nf = 0; nf < 4; nf++)
#pragma unroll
            for (int r = 0; r < 4; r++) acc[mf][nf][r] = 0.0f;

    const int nStages = K >> 4;

    uint32_t aDst = su(smem + aRow * A_STRIDE + aK0);
    uint32_t bDst0 = su(smem + 3 * A_STAGE + bK0 * B_STRIDE + bN0);
    uint32_t bDst1 = su(smem + 3 * A_STAGE + (bK0 + 8) * B_STRIDE + bN0);

#pragma unroll
    for (int s = 0; s < 2; s++) {
        int k0g = s * 16;
        cp16(aDst + s * A_STAGE * 4, aSrc + k0g, ap);
        cp16(bDst0 + s * B_STAGE * 4, bSrc0 + (size_t)k0g * N, true);
        cp16(bDst1 + s * B_STAGE * 4, bSrc1 + (size_t)k0g * N, true);
        asm volatile("cp.async.commit_group;");
    }

    for (int st = 0; st < nStages; st++) {
        if (nStages - st >= 2) asm volatile("cp.async.wait_group 1;" ::: "memory");
        else                   asm volatile("cp.async.wait_group 0;" ::: "memory");
        __syncthreads();

        const int cur = st % 3;
        const float* Asf = smem + cur * A_STAGE;
        const float* Bsf = smem + 3 * A_STAGE + cur * B_STAGE;

#pragma unroll
        for (int kk = 0; kk < 2; kk++) {
            const int k0 = kk * 8;
            uint32_t af[2][4], bf[4][2];
#pragma unroll
            for (int mf = 0; mf < 2; mf++) {
                int r0 = wm * 32 + mf * 16 + g;
                float a0 = Asf[r0 * A_STRIDE + k0 + t];
                float a1 = Asf[(r0 + 8) * A_STRIDE + k0 + t];
                float a2 = Asf[r0 * A_STRIDE + k0 + t + 4];
                float a3 = Asf[(r0 + 8) * A_STRIDE + k0 + t + 4];
                if (CVTA) {
                    af[mf][0] = f2tf32(a0); af[mf][1] = f2tf32(a1);
                    af[mf][2] = f2tf32(a2); af[mf][3] = f2tf32(a3);
                } else {
                    af[mf][0] = __float_as_uint(a0); af[mf][1] = __float_as_uint(a1);
                    af[mf][2] = __float_as_uint(a2); af[mf][3] = __float_as_uint(a3);
                }
            }
#pragma unroll
            for (int nf = 0; nf < 4; nf++) {
                int n0 = wn * 32 + nf * 8 + g;
                bf[nf][0] = __float_as_uint(Bsf[(k0 + t) * B_STRIDE + n0]);
                bf[nf][1] = __float_as_uint(Bsf[(k0 + t + 4) * B_STRIDE + n0]);
            }
#pragma unroll
            for (int mf = 0; mf < 2; mf++)
#pragma unroll
                for (int nf = 0; nf < 4; nf++)
                    mma_tf32(acc[mf][nf], af[mf], bf[nf]);
        }

        if (st + 2 < nStages) {
            int s = (st + 2) % 3;
            int k0g = (st + 2) * 16;
            cp16(aDst + s * A_STAGE * 4, aSrc + k0g, ap);
            cp16(bDst0 + s * B_STAGE * 4, bSrc0 + (size_t)k0g * N, true);
            cp16(bDst1 + s * B_STAGE * 4, bSrc1 + (size_t)k0g * N, true);
            asm volatile("cp.async.commit_group;");
        }
    }

    if (!FUSE) {
#pragma unroll
        for (int mf = 0; mf < 2; mf++) {
            int row0 = rowBase + wm * 32 + mf * 16 + g;
#pragma unroll
            for (int nf = 0; nf < 4; nf++) {
                int col = colBase + wn * 32 + nf * 8 + 2 * t;
                float b0 = bias ? bias[col] : 0.f;
                float b1 = bias ? bias[col + 1] : 0.f;
                if (row0 < M) {
                    float2 v = make_float2(acc[mf][nf][0] + b0, acc[mf][nf][1] + b1);
                    *(float2*)(C + (size_t)row0 * N + col) = v;
                }
                if (row0 + 8 < M) {
                    float2 v = make_float2(acc[mf][nf][2] + b0, acc[mf][nf][3] + b1);
                    *(float2*)(C + (size_t)(row0 + 8) * N + col) = v;
                }
            }
        }
    } else {
        float elp[2][2] = {}, erp[2][2] = {};   // [mf][rh]
#pragma unroll
        for (int nf = 0; nf < 4; nf++) {
            int col = wn * 32 + nf * 8 + 2 * t;
            float la0 = al[col], la1 = al[col + 1];
            float ra0 = ar[col], ra1 = ar[col + 1];
#pragma unroll
            for (int mf = 0; mf < 2; mf++) {
                elp[mf][0] += acc[mf][nf][0] * la0 + acc[mf][nf][1] * la1;
                elp[mf][1] += acc[mf][nf][2] * la0 + acc[mf][nf][3] * la1;
                erp[mf][0] += acc[mf][nf][0] * ra0 + acc[mf][nf][1] * ra1;
                erp[mf][1] += acc[mf][nf][2] * ra0 + acc[mf][nf][3] * ra1;
                int row0 = rowBase + wm * 32 + mf * 16 + g;
                if (row0 < M) {
                    __half2 hv = __floats2half2_rn(acc[mf][nf][0], acc[mf][nf][1]);
                    *(__half2*)(g_Whh + (size_t)row0 * DHID + col) = hv;
                }
                if (row0 + 8 < M) {
                    __half2 hv = __floats2half2_rn(acc[mf][nf][2], acc[mf][nf][3]);
                    *(__half2*)(g_Whh + (size_t)(row0 + 8) * DHID + col) = hv;
                }
            }
        }
#pragma unroll
        for (int mf = 0; mf < 2; mf++)
#pragma unroll
            for (int rh = 0; rh < 2; rh++) {
                float v = elp[mf][rh];
                v += __shfl_xor_sync(0xFFFFFFFFu, v, 1);
                v += __shfl_xor_sync(0xFFFFFFFFu, v, 2);
                elp[mf][rh] = v;
                float w = erp[mf][rh];
                w += __shfl_xor_sync(0xFFFFFFFFu, w, 1);
                w += __shfl_xor_sync(0xFFFFFFFFu, w, 2);
                erp[mf][rh] = w;
            }
        if (t == 0) {
#pragma unroll
            for (int mf = 0; mf < 2; mf++)
#pragma unroll
                for (int rh = 0; rh < 2; rh++) {
                    int gr = rowBase + wm * 32 + mf * 16 + g + rh * 8;
                    if (gr < M) {
                        g_el[gr * NH + wn] = elp[mf][rh];
                        g_er[gr * NH + wn] = erp[mf][rh];
                    }
                }
        }
    }
}

// ---------------- streams/events for fork-join + func attrs ----------------
static cudaStream_t g_s2;
static cudaEvent_t g_evFork, g_evCsr;
struct HostInit {
    HostInit() {
        cudaStreamCreateWithFlags(&g_s2, cudaStreamNonBlocking);
        cudaEventCreateWithFlags(&g_evFork, cudaEventDisableTiming);
        cudaEventCreateWithFlags(&g_evCsr, cudaEventDisableTiming);
        cudaFuncSetAttribute((const void*)gemm_tc<0, 0>, cudaFuncAttributeMaxDynamicSharedMemorySize, SMEM_BYTES);
        cudaFuncSetAttribute((const void*)gemm_tc<1, 0>, cudaFuncAttributeMaxDynamicSharedMemorySize, SMEM_BYTES);
        cudaFuncSetAttribute((const void*)gemm_tc<1, 1>, cudaFuncAttributeMaxDynamicSharedMemorySize, SMEM_BYTES);
    }
};
static HostInit g_hostInit;

// ================= CSR build (int4-vectorized, epos-based) =================
__global__ void k_count(const int4* __restrict__ dst4) {
    int i = blockIdx.x * blockDim.x + threadIdx.x;
    if (i >= NE / 4) return;
    int4 d = dst4[i];
    int4 p;
    p.x = atomicAdd(&g_cnt[d.x], 1);
    p.y = atomicAdd(&g_cnt[d.y], 1);
    p.z = atomicAdd(&g_cnt[d.z], 1);
    p.w = atomicAdd(&g_cnt[d.w], 1);
    ((int4*)g_epos)[i] = p;
}

__global__ void k_scan() {
    __shared__ int warpsum[32];
    const int T = 1024;
    const int CH = (NN + T - 1) / T;
    int t = threadIdx.x;
    int lane = t & 31, wid = t >> 5;
    int lo = t * CH;
    int hi = lo + CH; if (hi > NN) hi = NN;
    if (lo > NN) lo = NN;
    int s = 0;
    for (int i = lo; i < hi; i++) s += g_cnt[i];
    int v = s;
#pragma unroll
    for (int o = 1; o < 32; o <<= 1) {
        int u = __shfl_up_sync(0xFFFFFFFFu, v, o);
        if (lane >= o) v += u;
    }
    if (lane == 31) warpsum[wid] = v;
    __syncthreads();
    if (wid == 0) {
        int w = warpsum[lane];
#pragma unroll
        for (int o = 1; o < 32; o <<= 1) {
            int u = __shfl_up_sync(0xFFFFFFFFu, w, o);
            if (lane >= o) w += u;
        }
        warpsum[lane] = w;
    }
    __syncthreads();
    int excl = v - s + (wid > 0 ? warpsum[wid - 1] : 0);
    int run = excl;
    for (int i = lo; i < hi; i++) {
        g_rowptr[i] = run;
        run += g_cnt[i];
    }
    if (t == T - 1) g_rowptr[NN] = run;
}

__global__ void k_fill(const int4* __restrict__ src4, const int4* __restrict__ dst4) {
    int i = blockIdx.x * blockDim.x + threadIdx.x;
    if (i >= NE / 4) return;
    int4 s = src4[i];
    int4 d = dst4[i];
    int4 p = ((const int4*)g_epos)[i];
    g_csrc[g_rowptr[d.x] + p.x] = s.x;
    g_csrc[g_rowptr[d.y] + p.y] = s.y;
    g_csrc[g_rowptr[d.z] + p.z] = s.z;
    g_csrc[g_rowptr[d.w] + p.w] = s.w;
}

// ================= fused softmax + aggregate (warp per node, smem exp stage) ====
// R7 form: 256 threads = 8 nodes per block, unroll 8.
// LAYER==1 stores tf32-rounded z; LAYER==2 stores tf32-rounded z2.
template <int LAYER>
__global__ void k_gat_agg(const float* __restrict__ bias) {
    __shared__ float exsAll[8][128];
    int wIn = threadIdx.x >> 5;
    int n = (blockIdx.x << 3) + wIn;
    if (n >= NN) return;
    float* exsw = exsAll[wIn];
    int lane = threadIdx.x & 31;
    int myh = lane >> 3;
    int beg = g_rowptr[n], end = g_rowptr[n + 1];
    float4 er4 = *(const float4*)(g_er + n * NH);

    float ax = 0.f, ay = 0.f, az = 0.f, aw = 0.f;
    float se0 = 0.f, se1 = 0.f, se2 = 0.f, se3 = 0.f;
    const __half* WhBase = g_Whh + (size_t)(lane * 4);

    for (int base = beg; base < end; base += 32) {
        int cnt = end - base; if (cnt > 32) cnt = 32;
        int sv = 0;
        float4 elv = make_float4(0.f, 0.f, 0.f, 0.f);
        if (lane < cnt) {
            sv = g_csrc[base + lane];
            elv = *(const float4*)(g_el + sv * NH);
        }
        float e0 = __expf(lrelu(elv.x + er4.x));
        float e1 = __expf(lrelu(elv.y + er4.y));
        float e2 = __expf(lrelu(elv.z + er4.z));
        float e3 = __expf(lrelu(elv.w + er4.w));
        if (lane >= cnt) { e0 = e1 = e2 = e3 = 0.f; }
        se0 += e0; se1 += e1; se2 += e2; se3 += e3;
        __syncwarp();
        *(float4*)&exsw[lane * 4] = make_float4(e0, e1, e2, e3);
        __syncwarp();
#pragma unroll 8
        for (int j = 0; j < cnt; j++) {
            int s = __shfl_sync(0xFFFFFFFFu, sv, j);
            float exh = exsw[j * 4 + myh];
            uint2 u = *(const uint2*)(WhBase + (size_t)s * DHID);
            float2 f0 = __half22float2(*(__half2*)&u.x);
            float2 f1 = __half22float2(*(__half2*)&u.y);
            ax = fmaf(exh, f0.x, ax);
            ay = fmaf(exh, f0.y, ay);
            az = fmaf(exh, f1.x, az);
            aw = fmaf(exh, f1.y, aw);
        }
    }
#pragma unroll
    for (int o = 16; o > 0; o >>= 1) {
        se0 += __shfl_xor_sync(0xFFFFFFFFu, se0, o);
        se1 += __shfl_xor_sync(0xFFFFFFFFu, se1, o);
        se2 += __shfl_xor_sync(0xFFFFFFFFu, se2, o);
        se3 += __shfl_xor_sync(0xFFFFFFFFu, se3, o);
    }
    float seh = myh < 2 ? (myh == 0 ? se0 : se1) : (myh == 2 ? se2 : se3);
    float r = 1.0f / (seh + EPSV);
    ax *= r; ay *= r; az *= r; aw *= r;

    if (LAYER == 1) {
        int d = lane * 4;
        float4 v;
        v.x = ax + bias[d + 0];
        v.y = ay + bias[d + 1];
        v.z = az + bias[d + 2];
        v.w = aw + bias[d + 3];
        v.x = v.x > 0.f ? v.x : (__expf(v.x) - 1.0f);
        v.y = v.y > 0.f ? v.y : (__expf(v.y) - 1.0f);
        v.z = v.z > 0.f ? v.z : (__expf(v.z) - 1.0f);
        v.w = v.w > 0.f ? v.w : (__expf(v.w) - 1.0f);
        // pre-round to tf32 so GEMM2 can skip A-side cvt (bit-identical result)
        v.x = round_tf32(v.x); v.y = round_tf32(v.y);
        v.z = round_tf32(v.z); v.w = round_tf32(v.w);
        *(float4*)(g_z + (size_t)n * DHID + d) = v;
    } else {
        int d = lane * 4;
        ax += bias[d + 0]; ay += bias[d + 1]; az += bias[d + 2]; aw += bias[d + 3];
#pragma unroll
        for (int o = 8; o <= 16; o <<= 1) {
            ax += __shfl_xor_sync(0xFFFFFFFFu, ax, o);
            ay += __shfl_xor_sync(0xFFFFFFFFu, ay, o);
            az += __shfl_xor_sync(0xFFFFFFFFu, az, o);
            aw += __shfl_xor_sync(0xFFFFFFFFu, aw, o);
        }
        if (lane < 8) {
            float4 v = make_float4(round_tf32(0.25f * ax), round_tf32(0.25f * ay),
                                   round_tf32(0.25f * az), round_tf32(0.25f * aw));
            *(float4*)(g_z2 + (size_t)n * DHEAD + lane * 4) = v;
        }
    }
}

// ================= launch =================
extern "C" void kernel_launch(void* const* d_in, const int* in_sizes, int n_in,
                              void* d_out, int out_size) {
    const float* h   = (const float*)d_in[0];
    const int*   src = (const int*)d_in[1];
    const int*   dst = (const int*)d_in[2];
    const float* W1  = (const float*)d_in[3];
    const float* al1 = (const float*)d_in[4];
    const float* ar1 = (const float*)d_in[5];
    const float* b1  = (const float*)d_in[6];
    const float* W2  = (const float*)d_in[7];
    const float* al2 = (const float*)d_in[8];
    const float* ar2 = (const float*)d_in[9];
    const float* b2  = (const float*)d_in[10];
    const float* Wp  = (const float*)d_in[11];
    const float* bp  = (const float*)d_in[12];
    float* out = (float*)d_out;

    float *p_z, *p_z2, *p_W1t, *p_W2t, *p_Wpt;
    int *p_cnt;
    cudaGetSymbolAddress((void**)&p_z,   g_z);
    cudaGetSymbolAddress((void**)&p_z2,  g_z2);
    cudaGetSymbolAddress((void**)&p_cnt, g_cnt);
    cudaGetSymbolAddress((void**)&p_W1t, g_W1t);
    cudaGetSymbolAddress((void**)&p_W2t, g_W2t);
    cudaGetSymbolAddress((void**)&p_Wpt, g_Wpt);

    const int TPB = 256;
    int gEdge4 = (NE / 4 + TPB - 1) / TPB;
    int gAgg   = (NN + 7) / 8;

    dim3 gemmGrid1(1, (NN + 63) / 64);              // N=128
    dim3 gemmGridP(OUTD / 128, (NN + 63) / 64);     // N=512

    // ---- fork: CSR build on side stream, weights+GEMM1 on main stream ----
    cudaEventRecord(g_evFork, 0);
    cudaStreamWaitEvent(g_s2, g_evFork, 0);
    cudaMemsetAsync(p_cnt, 0, NN * sizeof(int), g_s2);
    k_count<<<gEdge4, TPB, 0, g_s2>>>((const int4*)dst);
    k_scan<<<1, 1024, 0, g_s2>>>();
    k_fill<<<gEdge4, TPB, 0, g_s2>>>((const int4*)src, (const int4*)dst);
    cudaEventRecord(g_evCsr, g_s2);

    // pre-round all weights to tf32 (49152 elements)
    k_round_weights<<<192, 256>>>(W1, W2, Wp);

    // ===== layer 1 =====  (A = h: cvt at load; B = pre-rounded W1)
    gemm_tc<1, 1><<<gemmGrid1, 256, SMEM_BYTES>>>(h, p_W1t, nullptr, nullptr,
                                                  NN, DHID, DHID, al1, ar1);
    cudaStreamWaitEvent(0, g_evCsr, 0);   // join: agg needs CSR
    k_gat_agg<1><<<gAgg, 256>>>(b1);

    // ===== layer 2 =====  (A = pre-rounded z; B = pre-rounded W2: no cvts)
    gemm_tc<1, 0><<<gemmGrid1, 256, SMEM_BYTES>>>(p_z, p_W2t, nullptr, nullptr,
                                                  NN, DHID, DHID, al2, ar2);
    k_gat_agg<2><<<gAgg, 256>>>(b2);

    // ===== projection head =====  (A = pre-rounded z2; B = pre-rounded Wp)
    gemm_tc<0, 0><<<gemmGridP, 256, SMEM_BYTES>>>(p_z2, p_Wpt, bp, out,
                                                  NN, OUTD, DHEAD, nullptr, nullptr);
}